// round 6
// baseline (speedup 1.0000x reference)
#include <cuda_runtime.h>
#include <cuda_bf16.h>

#define FULL_MASK 0xFFFFFFFFu

// Store-first / patch-later:
//  Phase 1: blanket-store the cond=true pattern (dist=0, nidx=[row,-1,...])
//           for the warp's 8 rows — constants only, no loads, issues at t=0,
//           so the 512MB store stream overlaps the whole decide phase.
//  Phase 2: 4 lanes/row early-exit gather scan over columns 1..63 to decide
//           whether any neighbour score beats score[row] (strict >).
//  Phase 3: ~12% of warps have a cond=false row; those rows (~1.6% of all)
//           are re-loaded and overwritten. Same thread rewrites the same
//           addresses it wrote in phase 1 -> program order makes it correct.
__global__ void __launch_bounds__(256)
dgb_kernel(const float4* __restrict__ dist4,
           const int*    __restrict__ nidx,
           const float*  __restrict__ score,
           float4* __restrict__ dist_out4,
           float4* __restrict__ nidx_out4,
           long long V)
{
    long long warp_id = ((long long)blockIdx.x * blockDim.x + threadIdx.x) >> 5;
    int lane = threadIdx.x & 31;
    int g = lane >> 2;                    // row group within warp: 0..7
    int l = lane & 3;                     // lane within group: 0..3
    unsigned grpmask = 0xFu << (g << 2);

    long long warp_row0 = warp_id * 8;
    long long gbase = warp_row0 * 16;     // float4 index of warp region
    long long row = warp_row0 + g;
    bool valid = row < V;

    // ---- phase 1: dependency-free blanket stores (cond=true pattern) ----
    #pragma unroll
    for (int t = 0; t < 4; ++t) {
        int vec = t * 32 + lane;          // 0..127 within warp region
        int rl = vec >> 4;                // row_local 0..7
        int within = vec & 15;            // float4 within row
        long long rr = warp_row0 + rl;
        if (rr >= V) continue;
        float4 nv = make_float4(-1.f, -1.f, -1.f, -1.f);
        if (within == 0) nv.x = (float)rr;
        dist_out4[gbase + vec] = make_float4(0.f, 0.f, 0.f, 0.f);
        nidx_out4[gbase + vec] = nv;
    }

    // ---- phase 2: early-exit decide (columns 1..63; col 0 is self) ----
    float sv = valid ? __ldg(score + row) : 3.0f;   // >1 => never beaten
    const int* nrow = nidx + (valid ? row : 0) * 64;

    bool cond = false;                    // true => some neighbour beats sv
    #pragma unroll 1
    for (int j = 0; j < 16; ++j) {
        int col = (j << 2) + 1 + l;       // 1..64 (l=3,j=15 guarded below)
        bool beat = false;
        if (col < 64) {
            int ni = __ldg(nrow + col);
            if (ni >= 0)
                beat = __ldg(score + ni) > sv;   // strict: matches diff < 0
        }
        if (__any_sync(grpmask, beat)) { cond = true; break; }
    }

    unsigned bal = __ballot_sync(FULL_MASK, cond);

    // ---- phase 3: patch the rare cond=false rows ----
    // cond is group-uniform, so bal is blocks of 4 identical bits;
    // all-rows-true <=> bal == 0xFFFFFFFF. Tail (invalid) rows enter here
    // with bit 0 but are skipped by the rr < V guard.
    if (bal != FULL_MASK) {
        const int4* nidx4 = (const int4*)nidx;
        #pragma unroll
        for (int t = 0; t < 4; ++t) {
            int vec = t * 32 + lane;
            int rl = vec >> 4;
            long long rr = warp_row0 + rl;
            bool c = (bal >> (rl << 2)) & 1u;
            if (!c && rr < V) {
                long long idx = gbase + vec;
                float4 dv = __ldg(dist4 + idx);
                int4 ni = __ldg(nidx4 + idx);
                dist_out4[idx] = dv;
                nidx_out4[idx] = make_float4((float)ni.x, (float)ni.y,
                                             (float)ni.z, (float)ni.w);
            }
        }
    }
}

extern "C" void kernel_launch(void* const* d_in, const int* in_sizes, int n_in,
                              void* d_out, int out_size)
{
    const float* dist  = (const float*)d_in[0];   // [V, 64] f32
    const int*   nidx  = (const int*)d_in[1];     // [V, 64] i32
    const float* score = (const float*)d_in[2];   // [V, 1]  f32

    long long V = in_sizes[2];                    // score element count == V

    float* out      = (float*)d_out;
    float* dist_out = out;                        // first V*64 floats
    float* nidx_out = out + V * 64;               // second V*64 (ints as f32)

    // 4 lanes per row -> V*4 threads
    long long total_threads = V * 4;
    int threads = 256;
    long long blocks = (total_threads + threads - 1) / threads;

    dgb_kernel<<<(unsigned int)blocks, threads>>>(
        (const float4*)dist, nidx, score,
        (float4*)dist_out, (float4*)nidx_out, V);
}

// round 7
// speedup vs baseline: 1.2388x; 1.2388x over previous
#include <cuda_runtime.h>
#include <cuda_bf16.h>

#define FULL_MASK 0xFFFFFFFFu

// R3 shape: 4 lanes per row, 8 rows per warp. Early-exit scan over columns
// 1..63 (column 0 = self, never gathered) in chunks of 4 with per-group exit.
// Score gathers use __ldcg (L2-only): the 4MB score table can't live in L1
// (>95% miss), so L1 line fills for gathers are pure wasted L1 bandwidth —
// bypassing them cuts l1tex work and leaves L1 to the nidx decide lines.
// Write phase streams the warp's 8 contiguous rows coalesced (512B/instr).
__global__ void __launch_bounds__(256)
dgb_kernel(const float4* __restrict__ dist4,
           const int*    __restrict__ nidx,
           const float*  __restrict__ score,
           float4* __restrict__ dist_out4,
           float4* __restrict__ nidx_out4,
           long long V)
{
    long long warp_id = ((long long)blockIdx.x * blockDim.x + threadIdx.x) >> 5;
    int lane = threadIdx.x & 31;
    int g = lane >> 2;                 // row group within warp: 0..7
    int l = lane & 3;                  // lane within group: 0..3
    unsigned grpmask = 0xFu << (g << 2);

    long long row = warp_id * 8 + g;
    bool valid = row < V;
    long long srow = valid ? row : 0;

    float sv = valid ? __ldg(score + row) : 3.0f;   // >1 => never beaten
    const int* nrow = nidx + srow * 64;

    // ---- early-exit decide: chunks of 4 over columns 1..63 ----
    bool cond = false;                 // true => some neighbour beats sv
    #pragma unroll 1
    for (int j = 0; j < 16; ++j) {
        int col = (j << 2) + 1 + l;    // 1..64 (64 guarded off)
        bool beat = false;
        if (col < 64) {
            int ni = __ldg(nrow + col);
            if (ni >= 0)
                beat = __ldcg(score + ni) > sv;   // strict: matches diff < 0
        }
        if (__any_sync(grpmask, beat)) { cond = true; break; }
    }

    // Publish cond bits for all 8 rows of this warp (bit at lane g*4).
    unsigned bal = __ballot_sync(FULL_MASK, cond);

    // ---- write phase: contiguous streaming over the warp's 8 rows ----
    long long warp_row0 = warp_id * 8;
    long long gbase = warp_row0 * 16;  // float4 index of region start
    const int4* nidx4 = (const int4*)nidx;

    #pragma unroll
    for (int t = 0; t < 4; ++t) {
        int vec = t * 32 + lane;       // 0..127 within warp region
        int row_local = vec >> 4;      // 0..7
        int within = vec & 15;         // float4 within row
        long long rr = warp_row0 + row_local;
        if (rr >= V) continue;
        long long idx = gbase + vec;

        bool c = (bal >> (row_local << 2)) & 1u;

        float4 dv, nv;
        if (c) {
            dv = make_float4(0.f, 0.f, 0.f, 0.f);
            nv = make_float4(-1.f, -1.f, -1.f, -1.f);
            if (within == 0) nv.x = (float)rr;
        } else {
            dv = __ldg(dist4 + idx);
            int4 niv = __ldg(nidx4 + idx);
            nv = make_float4((float)niv.x, (float)niv.y,
                             (float)niv.z, (float)niv.w);
        }
        dist_out4[idx] = dv;
        nidx_out4[idx] = nv;
    }
}

extern "C" void kernel_launch(void* const* d_in, const int* in_sizes, int n_in,
                              void* d_out, int out_size)
{
    const float* dist  = (const float*)d_in[0];   // [V, 64] f32
    const int*   nidx  = (const int*)d_in[1];     // [V, 64] i32
    const float* score = (const float*)d_in[2];   // [V, 1]  f32

    long long V = in_sizes[2];                    // score element count == V

    float* out      = (float*)d_out;
    float* dist_out = out;                        // first V*64 floats
    float* nidx_out = out + V * 64;               // second V*64 (ints as f32)

    // 4 lanes per row -> V*4 threads
    long long total_threads = V * 4;
    int threads = 256;
    long long blocks = (total_threads + threads - 1) / threads;

    dgb_kernel<<<(unsigned int)blocks, threads>>>(
        (const float4*)dist, nidx, score,
        (float4*)dist_out, (float4*)nidx_out, V);
}